// round 11
// baseline (speedup 1.0000x reference)
#include <cuda_runtime.h>
#include <cuda_fp16.h>
#include <cstdint>

#define SQ      4096
#define DD      64
#define QT      64           // q rows per CTA
#define KT      64           // keys per tile
#define NT      128          // threads (4 warps x 16 q rows)
#define NTILES  (SQ / KT)    // 64
#define BB      8

// fp16 scratch (converted once per launch by prologue kernel)
__device__ __half g_Qh[(size_t)BB * SQ * DD];   // [b][s][d], pre-scaled
__device__ __half g_Kh[(size_t)BB * SQ * DD];   // [b][s][d]
__device__ __half g_Vt[(size_t)BB * DD * SQ];   // [b][d][s]  (transposed)

#define SCALE (0.125f * 1.44269504088896340736f)   // 1/sqrt(64) * log2(e)

#define KPAD 36   // K row: 64 halfs = 32 words + 4 pad
#define VPAD 36   // V row: 64 halfs = 32 words + 4 pad

__device__ __forceinline__ uint32_t s2u(const void* p) {
    uint32_t a;
    asm("{ .reg .u64 t; cvta.to.shared.u64 t, %1; cvt.u32.u64 %0, t; }" : "=r"(a) : "l"(p));
    return a;
}
__device__ __forceinline__ void cp16(uint32_t d, const void* s) {
    asm volatile("cp.async.cg.shared.global [%0], [%1], 16;" :: "r"(d), "l"(s));
}
#define CP_COMMIT() asm volatile("cp.async.commit_group;" ::: "memory")
#define CP_WAIT(n)  asm volatile("cp.async.wait_group %0;" :: "n"(n) : "memory")

__device__ __forceinline__ float ex2(float x) {
    float r;
    asm("ex2.approx.ftz.f32 %0, %1;" : "=f"(r) : "f"(x));
    return r;
}
__device__ __forceinline__ uint32_t pk(float p0, float p1) {
    uint32_t r;
    asm("cvt.rn.f16x2.f32 %0, %1, %2;" : "=r"(r) : "f"(p1), "f"(p0));
    return r;
}
__device__ __forceinline__ void mma_f16(float* c, uint32_t a0, uint32_t a1, uint32_t a2,
                                        uint32_t a3, uint32_t b0, uint32_t b1) {
    asm volatile(
        "mma.sync.aligned.m16n8k16.row.col.f32.f16.f16.f32 "
        "{%0,%1,%2,%3}, {%4,%5,%6,%7}, {%8,%9}, {%0,%1,%2,%3};"
        : "+f"(c[0]), "+f"(c[1]), "+f"(c[2]), "+f"(c[3])
        : "r"(a0), "r"(a1), "r"(a2), "r"(a3), "r"(b0), "r"(b1));
}

// ---- fused prologue ----
#define NQK (BB * SQ * DD / 4 / 256)        // 2048 blocks: Q/K convert
#define NVT (BB * (SQ / 64))                // 512 blocks: V transpose

__global__ void __launch_bounds__(256)
cvt_all(const float* __restrict__ Q, const float* __restrict__ K,
        const float* __restrict__ V) {
    if (blockIdx.x < NQK) {
        int i = blockIdx.x * 256 + threadIdx.x;       // float4 index
        float4 q = ((const float4*)Q)[i];
        float4 k = ((const float4*)K)[i];
        __half2* qo = (__half2*)g_Qh;
        __half2* ko = (__half2*)g_Kh;
        qo[2 * i]     = __floats2half2_rn(q.x * SCALE, q.y * SCALE);
        qo[2 * i + 1] = __floats2half2_rn(q.z * SCALE, q.w * SCALE);
        ko[2 * i]     = __floats2half2_rn(k.x, k.y);
        ko[2 * i + 1] = __floats2half2_rn(k.z, k.w);
        return;
    }
    // ---- V transpose tile: batch b, s-range [s0, s0+64) ----
    __shared__ float tl[64][65];
    const int vb  = blockIdx.x - NQK;
    const int b   = vb >> 6;
    const int s0  = (vb & 63) * 64;
    const int tid = threadIdx.x;

    const float* src = V + ((size_t)b * SQ + s0) * DD;
    #pragma unroll
    for (int i = 0; i < 16; i++) {
        int idx = tid + i * 256;
        tl[idx >> 6][idx & 63] = src[idx];            // coalesced read
    }
    __syncthreads();

    __half* dst = g_Vt + (size_t)b * DD * SQ + s0;
    #pragma unroll
    for (int i = 0; i < 2; i++) {
        int c  = tid + i * 256;
        int d  = c >> 3;
        int sc = (c & 7) * 8;
        __half h[8];
        #pragma unroll
        for (int j = 0; j < 8; j++) h[j] = __float2half_rn(tl[sc + j][d]);
        *(uint4*)(dst + (size_t)d * SQ + sc) = *(uint4*)h;   // coalesced 16B write
    }
}

__global__ void __launch_bounds__(NT, 4)
attn_mma(const float* __restrict__ Mask, float* __restrict__ O) {
    __shared__ uint32_t Ks[2][KT * KPAD];   // keys x d(halfs)
    __shared__ uint32_t Vs[2][DD * VPAD];   // d x keys(halfs)

    const int tid  = threadIdx.x;
    const int w    = tid >> 5;
    const int lane = tid & 31;
    const int g    = lane >> 2;
    const int q    = lane & 3;

    const int b  = blockIdx.y;
    const int qb = blockIdx.x * QT;
    const __half* Kg = g_Kh + (size_t)b * SQ * DD;
    const __half* Vg = g_Vt + (size_t)b * DD * SQ;

    const uint32_t ks_u = s2u(Ks);
    const uint32_t vs_u = s2u(Vs);

    auto load_kv = [&](int tile) {
        const int slot = tile & 1;
        const __half* kt = Kg + (size_t)tile * KT * DD;
        const __half* vt = Vg + tile * KT;            // V row stride SQ
        #pragma unroll
        for (int i = 0; i < 8; i++) {
            int c = tid + i * NT;                     // 0..1023
            if (c < 512) {                            // K: 64 rows x 8 chunks
                int row = c >> 3, sub = c & 7;
                cp16(ks_u + (uint32_t)(slot * KT * KPAD + row * KPAD + sub * 4) * 4,
                     kt + row * DD + sub * 8);
            } else {                                  // V: 64 rows x 8 chunks
                int c2 = c - 512;
                int row = c2 >> 3, sub = c2 & 7;
                cp16(vs_u + (uint32_t)(slot * DD * VPAD + row * VPAD + sub * 4) * 4,
                     vt + (size_t)row * SQ + sub * 8);
            }
        }
        CP_COMMIT();
    };
    load_kv(0);

    // ---- resident Q A-fragments: 4 k-blocks x 4 regs (16 q rows) ----
    const int r0 = qb + w * 16 + g;
    uint32_t qa[4][4];
    {
        const uint32_t* Qw = (const uint32_t*)(g_Qh + (size_t)b * SQ * DD);
        #pragma unroll
        for (int kb = 0; kb < 4; kb++) {
            int col = kb * 8 + q;
            qa[kb][0] = Qw[r0 * 32 + col];
            qa[kb][1] = Qw[(r0 + 8) * 32 + col];
            qa[kb][2] = Qw[r0 * 32 + col + 4];
            qa[kb][3] = Qw[(r0 + 8) * 32 + col + 4];
        }
    }

    float o[8][4];
    #pragma unroll
    for (int j = 0; j < 8; j++)
        #pragma unroll
        for (int i = 0; i < 4; i++) o[j][i] = 0.0f;

    float lacc0 = 0.0f, lacc1 = 0.0f;

    for (int t = 0; t < NTILES; t++) {
        const int slot = t & 1;

        CP_WAIT(0);
        __syncthreads();      // tile t ready AND every warp done with tile t-1
        if (t + 1 < NTILES) load_kv(t + 1);

        const uint32_t* Kslot = Ks[slot];
        const uint32_t* Vslot = Vs[slot];

        #pragma unroll
        for (int kk = 0; kk < 4; kk++) {      // 16 keys per kk
            uint32_t pa[4];

            // ---- QK: 4 independent chains of depth 2 (jj x kb-half) ----
            {
                float cA[2][4], cB[2][4];
                #pragma unroll
                for (int jj = 0; jj < 2; jj++)
                    #pragma unroll
                    for (int i = 0; i < 4; i++) { cA[jj][i] = 0.f; cB[jj][i] = 0.f; }

                const uint32_t* kr0 = Kslot + (16 * kk + g) * KPAD + q;
                const uint32_t* kr1 = Kslot + (16 * kk + 8 + g) * KPAD + q;

                #pragma unroll
                for (int kb = 0; kb < 2; kb++) {
                    uint32_t b00 = kr0[kb * 8], b01 = kr0[kb * 8 + 4];
                    uint32_t b10 = kr1[kb * 8], b11 = kr1[kb * 8 + 4];
                    mma_f16(cA[0], qa[kb][0], qa[kb][1], qa[kb][2], qa[kb][3], b00, b01);
                    mma_f16(cA[1], qa[kb][0], qa[kb][1], qa[kb][2], qa[kb][3], b10, b11);
                }
                #pragma unroll
                for (int kb = 2; kb < 4; kb++) {
                    uint32_t b00 = kr0[kb * 8], b01 = kr0[kb * 8 + 4];
                    uint32_t b10 = kr1[kb * 8], b11 = kr1[kb * 8 + 4];
                    mma_f16(cB[0], qa[kb][0], qa[kb][1], qa[kb][2], qa[kb][3], b00, b01);
                    mma_f16(cB[1], qa[kb][0], qa[kb][1], qa[kb][2], qa[kb][3], b10, b11);
                }

                #pragma unroll
                for (int jj = 0; jj < 2; jj++) {
                    float s0 = cA[jj][0] + cB[jj][0];
                    float s1 = cA[jj][1] + cB[jj][1];
                    float s2 = cA[jj][2] + cB[jj][2];
                    float s3 = cA[jj][3] + cB[jj][3];
                    float p0 = ex2(s0);     // logits already in log2 domain
                    float p1 = ex2(s1);
                    float p2 = ex2(s2);
                    float p3 = ex2(s3);
                    lacc0 += p0 + p1;
                    lacc1 += p2 + p3;
                    pa[jj * 2]     = pk(p0, p1);
                    pa[jj * 2 + 1] = pk(p2, p3);
                }
            }

            // ---- O += P(kk) . V ----
            const uint32_t* vr = Vslot + kk * 8 + q;
            #pragma unroll
            for (int j2 = 0; j2 < 8; j2++) {
                uint32_t b0 = vr[(8 * j2 + g) * VPAD];
                uint32_t b1 = vr[(8 * j2 + g) * VPAD + 4];
                mma_f16(o[j2], pa[0], pa[1], pa[2], pa[3], b0, b1);
            }
        }
    }

    // ---- epilogue: reduce row sums, normalize, mask, store ----
    lacc0 += __shfl_xor_sync(0xffffffffu, lacc0, 1);
    lacc0 += __shfl_xor_sync(0xffffffffu, lacc0, 2);
    lacc1 += __shfl_xor_sync(0xffffffffu, lacc1, 1);
    lacc1 += __shfl_xor_sync(0xffffffffu, lacc1, 2);

    const int row0 = r0;
    const int row1 = r0 + 8;
    const float inv0 = Mask[(size_t)b * SQ + row0] / lacc0;
    const float inv1 = Mask[(size_t)b * SQ + row1] / lacc1;

    float* o0 = O + ((size_t)b * SQ + row0) * DD;
    float* o1 = O + ((size_t)b * SQ + row1) * DD;
    #pragma unroll
    for (int j = 0; j < 8; j++) {
        float2 v0 = make_float2(o[j][0] * inv0, o[j][1] * inv0);
        float2 v1 = make_float2(o[j][2] * inv1, o[j][3] * inv1);
        *(float2*)(o0 + 8 * j + 2 * q) = v0;
        *(float2*)(o1 + 8 * j + 2 * q) = v1;
    }
}

extern "C" void kernel_launch(void* const* d_in, const int* in_sizes, int n_in,
                              void* d_out, int out_size) {
    const float* q    = (const float*)d_in[0];
    const float* k    = (const float*)d_in[1];
    const float* v    = (const float*)d_in[2];
    const float* mask = (const float*)d_in[3];
    float* out        = (float*)d_out;

    cvt_all<<<NQK + NVT, 256>>>(q, k, v);

    dim3 grid(SQ / QT, BB);
    attn_mma<<<grid, NT>>>(mask, out);
}

// round 12
// speedup vs baseline: 1.1658x; 1.1658x over previous
#include <cuda_runtime.h>
#include <cuda_fp16.h>
#include <cstdint>

#define SQ      4096
#define DD      64
#define QT      128          // q rows per CTA
#define KT      128          // keys per tile
#define NT      128          // threads (4 warps x 32 q rows)
#define NTILES  (SQ / KT)    // 32
#define BB      8

// fp16 scratch (converted once per launch by prologue kernel)
__device__ __half g_Qh[(size_t)BB * SQ * DD];   // [b][s][d], pre-scaled
__device__ __half g_Kh[(size_t)BB * SQ * DD];   // [b][s][d]
__device__ __half g_Vt[(size_t)BB * DD * SQ];   // [b][d][s]  (transposed)

#define SCALE (0.125f * 1.44269504088896340736f)   // 1/sqrt(64) * log2(e)

#define KPAD 36   // K row: 64 halfs = 32 words + 4 pad
#define VPAD 68   // V row: 128 halfs = 64 words + 4 pad

__device__ __forceinline__ uint32_t s2u(const void* p) {
    uint32_t a;
    asm("{ .reg .u64 t; cvta.to.shared.u64 t, %1; cvt.u32.u64 %0, t; }" : "=r"(a) : "l"(p));
    return a;
}
__device__ __forceinline__ void cp16(uint32_t d, const void* s) {
    asm volatile("cp.async.cg.shared.global [%0], [%1], 16;" :: "r"(d), "l"(s));
}
#define CP_COMMIT() asm volatile("cp.async.commit_group;" ::: "memory")
#define CP_WAIT(n)  asm volatile("cp.async.wait_group %0;" :: "n"(n) : "memory")

__device__ __forceinline__ float ex2(float x) {
    float r;
    asm("ex2.approx.ftz.f32 %0, %1;" : "=f"(r) : "f"(x));
    return r;
}
__device__ __forceinline__ uint32_t pk(float p0, float p1) {
    uint32_t r;
    asm("cvt.rn.f16x2.f32 %0, %1, %2;" : "=r"(r) : "f"(p1), "f"(p0));
    return r;
}
__device__ __forceinline__ void mma_f16(float* c, const uint32_t* a, uint32_t b0, uint32_t b1) {
    asm volatile(
        "mma.sync.aligned.m16n8k16.row.col.f32.f16.f16.f32 "
        "{%0,%1,%2,%3}, {%4,%5,%6,%7}, {%8,%9}, {%0,%1,%2,%3};"
        : "+f"(c[0]), "+f"(c[1]), "+f"(c[2]), "+f"(c[3])
        : "r"(a[0]), "r"(a[1]), "r"(a[2]), "r"(a[3]), "r"(b0), "r"(b1));
}

// ---- fused prologue ----
#define NQK (BB * SQ * DD / 4 / 256)        // 2048 blocks: Q/K convert
#define NVT (BB * (SQ / 64))                // 512 blocks: V transpose

__global__ void __launch_bounds__(256)
cvt_all(const float* __restrict__ Q, const float* __restrict__ K,
        const float* __restrict__ V) {
    if (blockIdx.x < NQK) {
        int i = blockIdx.x * 256 + threadIdx.x;       // float4 index
        float4 q = ((const float4*)Q)[i];
        float4 k = ((const float4*)K)[i];
        __half2* qo = (__half2*)g_Qh;
        __half2* ko = (__half2*)g_Kh;
        qo[2 * i]     = __floats2half2_rn(q.x * SCALE, q.y * SCALE);
        qo[2 * i + 1] = __floats2half2_rn(q.z * SCALE, q.w * SCALE);
        ko[2 * i]     = __floats2half2_rn(k.x, k.y);
        ko[2 * i + 1] = __floats2half2_rn(k.z, k.w);
        return;
    }
    // ---- V transpose tile: batch b, s-range [s0, s0+64) ----
    __shared__ float tl[64][65];
    const int vb  = blockIdx.x - NQK;
    const int b   = vb >> 6;
    const int s0  = (vb & 63) * 64;
    const int tid = threadIdx.x;

    const float* src = V + ((size_t)b * SQ + s0) * DD;
    #pragma unroll
    for (int i = 0; i < 16; i++) {
        int idx = tid + i * 256;
        tl[idx >> 6][idx & 63] = src[idx];            // coalesced read
    }
    __syncthreads();

    __half* dst = g_Vt + (size_t)b * DD * SQ + s0;
    #pragma unroll
    for (int i = 0; i < 2; i++) {
        int c  = tid + i * 256;
        int d  = c >> 3;
        int sc = (c & 7) * 8;
        __half h[8];
        #pragma unroll
        for (int j = 0; j < 8; j++) h[j] = __float2half_rn(tl[sc + j][d]);
        *(uint4*)(dst + (size_t)d * SQ + sc) = *(uint4*)h;   // coalesced 16B write
    }
}

__global__ void __launch_bounds__(NT, 2)
attn_mma(const float* __restrict__ Mask, float* __restrict__ O) {
    __shared__ uint32_t Ks[2][KT * KPAD];   // keys x d(halfs)
    __shared__ uint32_t Vs[2][DD * VPAD];   // d x keys(halfs)

    const int tid  = threadIdx.x;
    const int w    = tid >> 5;
    const int lane = tid & 31;
    const int g    = lane >> 2;
    const int q    = lane & 3;

    const int b  = blockIdx.y;
    const int qb = blockIdx.x * QT;
    const __half* Kg = g_Kh + (size_t)b * SQ * DD;
    const __half* Vg = g_Vt + (size_t)b * DD * SQ;

    const uint32_t ks_u = s2u(Ks);
    const uint32_t vs_u = s2u(Vs);

    auto load_kv = [&](int tile) {
        const int slot = tile & 1;
        const __half* kt = Kg + (size_t)tile * KT * DD;
        const __half* vt = Vg + tile * KT;            // V row stride SQ
        #pragma unroll
        for (int i = 0; i < 16; i++) {
            int c = tid + i * NT;                     // 0..2047
            if (c < 1024) {                           // K: 128 rows x 8 chunks
                int row = c >> 3, sub = c & 7;
                cp16(ks_u + (uint32_t)(slot * KT * KPAD + row * KPAD + sub * 4) * 4,
                     kt + row * DD + sub * 8);
            } else {                                  // V: 64 rows x 16 chunks
                int c2 = c - 1024;
                int row = c2 >> 4, sub = c2 & 15;
                cp16(vs_u + (uint32_t)(slot * DD * VPAD + row * VPAD + sub * 4) * 4,
                     vt + (size_t)row * SQ + sub * 8);
            }
        }
        CP_COMMIT();
    };
    load_kv(0);

    // ---- resident Q A-fragments: 2 row-blocks x 4 k-blocks x 4 regs ----
    const int r0 = qb + w * 32 + g;
    uint32_t qa[2][4][4];
    {
        const uint32_t* Qw = (const uint32_t*)(g_Qh + (size_t)b * SQ * DD);
        #pragma unroll
        for (int m = 0; m < 2; m++) {
            #pragma unroll
            for (int kb = 0; kb < 4; kb++) {
                int rr = r0 + 16 * m;
                int col = kb * 8 + q;
                qa[m][kb][0] = Qw[rr * 32 + col];
                qa[m][kb][1] = Qw[(rr + 8) * 32 + col];
                qa[m][kb][2] = Qw[rr * 32 + col + 4];
                qa[m][kb][3] = Qw[(rr + 8) * 32 + col + 4];
            }
        }
    }

    float o[2][8][4];
    #pragma unroll
    for (int m = 0; m < 2; m++)
        #pragma unroll
        for (int j = 0; j < 8; j++)
            #pragma unroll
            for (int i = 0; i < 4; i++) o[m][j][i] = 0.0f;

    float lacc[2][2] = {{0.f, 0.f}, {0.f, 0.f}};

    for (int t = 0; t < NTILES; t++) {
        const int slot = t & 1;

        CP_WAIT(0);
        __syncthreads();      // tile t ready AND every warp done with tile t-1
        if (t + 1 < NTILES) load_kv(t + 1);

        const uint32_t* Kslot = Ks[slot];
        const uint32_t* Vslot = Vs[slot];

        // double-buffered score fragments: cb[buf][m][jj][4]
        float cb[2][2][2][4];
        uint32_t pa[2][4];

        // ---- QK for chunk kk into buffer cb[kk&1] (4 chains, depth 4) ----
        auto qk_issue = [&](int kk, float (*c)[2][4]) {
            #pragma unroll
            for (int m = 0; m < 2; m++)
                #pragma unroll
                for (int jj = 0; jj < 2; jj++)
                    #pragma unroll
                    for (int i = 0; i < 4; i++) c[m][jj][i] = 0.0f;

            const uint32_t* kr0 = Kslot + (16 * kk + g) * KPAD + q;
            const uint32_t* kr1 = Kslot + (16 * kk + 8 + g) * KPAD + q;
            #pragma unroll
            for (int kb = 0; kb < 4; kb++) {
                uint32_t b00 = kr0[kb * 8], b01 = kr0[kb * 8 + 4];
                uint32_t b10 = kr1[kb * 8], b11 = kr1[kb * 8 + 4];
                mma_f16(c[0][0], qa[0][kb], b00, b01);
                mma_f16(c[1][0], qa[1][kb], b00, b01);
                mma_f16(c[0][1], qa[0][kb], b10, b11);
                mma_f16(c[1][1], qa[1][kb], b10, b11);
            }
        };

        // ---- softmax chunk kk (scores issued one iteration ago) + PV ----
        auto softmax_pv = [&](int kk, float (*c)[2][4]) {
            #pragma unroll
            for (int m = 0; m < 2; m++) {
                #pragma unroll
                for (int jj = 0; jj < 2; jj++) {
                    float p0 = ex2(c[m][jj][0]);   // logits already in log2 domain
                    float p1 = ex2(c[m][jj][1]);
                    float p2 = ex2(c[m][jj][2]);
                    float p3 = ex2(c[m][jj][3]);
                    lacc[m][0] += p0 + p1;
                    lacc[m][1] += p2 + p3;
                    pa[m][jj * 2]     = pk(p0, p1);
                    pa[m][jj * 2 + 1] = pk(p2, p3);
                }
            }
            const uint32_t* vr = Vslot + kk * 8 + q;
            #pragma unroll
            for (int j2 = 0; j2 < 8; j2++) {
                uint32_t b0 = vr[(8 * j2 + g) * VPAD];
                uint32_t b1 = vr[(8 * j2 + g) * VPAD + 4];
                mma_f16(o[0][j2], pa[0], b0, b1);
                mma_f16(o[1][j2], pa[1], b0, b1);
            }
        };

        qk_issue(0, cb[0]);
        #pragma unroll
        for (int kk = 1; kk < 8; kk++) {
            qk_issue(kk, cb[kk & 1]);           // fills tensor pipe...
            softmax_pv(kk - 1, cb[(kk - 1) & 1]); // ...while MUFU handles kk-1
        }
        softmax_pv(7, cb[1]);                   // drain before tile barrier
    }

    // ---- epilogue: reduce row sums, normalize, mask, store ----
    #pragma unroll
    for (int m = 0; m < 2; m++) {
        lacc[m][0] += __shfl_xor_sync(0xffffffffu, lacc[m][0], 1);
        lacc[m][0] += __shfl_xor_sync(0xffffffffu, lacc[m][0], 2);
        lacc[m][1] += __shfl_xor_sync(0xffffffffu, lacc[m][1], 1);
        lacc[m][1] += __shfl_xor_sync(0xffffffffu, lacc[m][1], 2);

        const int row0 = r0 + 16 * m;
        const int row1 = row0 + 8;
        const float inv0 = Mask[(size_t)b * SQ + row0] / lacc[m][0];
        const float inv1 = Mask[(size_t)b * SQ + row1] / lacc[m][1];

        float* o0 = O + ((size_t)b * SQ + row0) * DD;
        float* o1 = O + ((size_t)b * SQ + row1) * DD;
        #pragma unroll
        for (int j = 0; j < 8; j++) {
            float2 v0 = make_float2(o[m][j][0] * inv0, o[m][j][1] * inv0);
            float2 v1 = make_float2(o[m][j][2] * inv1, o[m][j][3] * inv1);
            *(float2*)(o0 + 8 * j + 2 * q) = v0;
            *(float2*)(o1 + 8 * j + 2 * q) = v1;
        }
    }
}

extern "C" void kernel_launch(void* const* d_in, const int* in_sizes, int n_in,
                              void* d_out, int out_size) {
    const float* q    = (const float*)d_in[0];
    const float* k    = (const float*)d_in[1];
    const float* v    = (const float*)d_in[2];
    const float* mask = (const float*)d_in[3];
    float* out        = (float*)d_out;

    cvt_all<<<NQK + NVT, 256>>>(q, k, v);

    dim3 grid(SQ / QT, BB);
    attn_mma<<<grid, NT>>>(mask, out);
}

// round 13
// speedup vs baseline: 1.2476x; 1.0702x over previous
#include <cuda_runtime.h>
#include <cuda_fp16.h>
#include <cstdint>

#define SQ      4096
#define DD      64
#define QT      128          // q rows per CTA
#define KT      64           // keys per tile
#define NT      128          // threads (4 warps x 32 q rows)
#define NTILES  (SQ / KT)    // 64
#define BB      8

// fp16 scratch (converted once per launch by prologue kernel)
__device__ __half g_Qh[(size_t)BB * SQ * DD];   // [b][s][d], pre-scaled
__device__ __half g_Kh[(size_t)BB * SQ * DD];   // [b][s][d]
__device__ __half g_Vt[(size_t)BB * DD * SQ];   // [b][d][s]  (transposed)

#define SCALE (0.125f * 1.44269504088896340736f)   // 1/sqrt(64) * log2(e)

#define RPAD 36   // K/V tile row: 64 halfs = 32 words + 4 pad -> conflict-free

__device__ __forceinline__ uint32_t s2u(const void* p) {
    uint32_t a;
    asm("{ .reg .u64 t; cvta.to.shared.u64 t, %1; cvt.u32.u64 %0, t; }" : "=r"(a) : "l"(p));
    return a;
}
__device__ __forceinline__ void cp16(uint32_t d, const void* s) {
    asm volatile("cp.async.cg.shared.global [%0], [%1], 16;" :: "r"(d), "l"(s));
}
#define CP_COMMIT() asm volatile("cp.async.commit_group;" ::: "memory")
#define CP_WAIT(n)  asm volatile("cp.async.wait_group %0;" :: "n"(n) : "memory")

__device__ __forceinline__ float ex2(float x) {
    float r;
    asm("ex2.approx.ftz.f32 %0, %1;" : "=f"(r) : "f"(x));
    return r;
}
__device__ __forceinline__ uint32_t pk(float p0, float p1) {
    uint32_t r;
    asm("cvt.rn.f16x2.f32 %0, %1, %2;" : "=r"(r) : "f"(p1), "f"(p0));
    return r;
}
__device__ __forceinline__ void mma_f16(float* c, uint32_t a0, uint32_t a1, uint32_t a2,
                                        uint32_t a3, uint32_t b0, uint32_t b1) {
    asm volatile(
        "mma.sync.aligned.m16n8k16.row.col.f32.f16.f16.f32 "
        "{%0,%1,%2,%3}, {%4,%5,%6,%7}, {%8,%9}, {%0,%1,%2,%3};"
        : "+f"(c[0]), "+f"(c[1]), "+f"(c[2]), "+f"(c[3])
        : "r"(a0), "r"(a1), "r"(a2), "r"(a3), "r"(b0), "r"(b1));
}

// ---- fused prologue ----
#define NQK (BB * SQ * DD / 4 / 256)        // 2048 blocks: Q/K convert
#define NVT (BB * (SQ / 64))                // 512 blocks: V transpose

__global__ void __launch_bounds__(256)
cvt_all(const float* __restrict__ Q, const float* __restrict__ K,
        const float* __restrict__ V) {
    if (blockIdx.x < NQK) {
        int i = blockIdx.x * 256 + threadIdx.x;       // float4 index
        float4 q = ((const float4*)Q)[i];
        float4 k = ((const float4*)K)[i];
        __half2* qo = (__half2*)g_Qh;
        __half2* ko = (__half2*)g_Kh;
        qo[2 * i]     = __floats2half2_rn(q.x * SCALE, q.y * SCALE);
        qo[2 * i + 1] = __floats2half2_rn(q.z * SCALE, q.w * SCALE);
        ko[2 * i]     = __floats2half2_rn(k.x, k.y);
        ko[2 * i + 1] = __floats2half2_rn(k.z, k.w);
        return;
    }
    // ---- V transpose tile: batch b, s-range [s0, s0+64) ----
    __shared__ float tl[64][65];
    const int vb  = blockIdx.x - NQK;
    const int b   = vb >> 6;
    const int s0  = (vb & 63) * 64;
    const int tid = threadIdx.x;

    const float* src = V + ((size_t)b * SQ + s0) * DD;
    #pragma unroll
    for (int i = 0; i < 16; i++) {
        int idx = tid + i * 256;
        tl[idx >> 6][idx & 63] = src[idx];            // coalesced read
    }
    __syncthreads();

    __half* dst = g_Vt + (size_t)b * DD * SQ + s0;
    #pragma unroll
    for (int i = 0; i < 2; i++) {
        int c  = tid + i * 256;
        int d  = c >> 3;
        int sc = (c & 7) * 8;
        __half h[8];
        #pragma unroll
        for (int j = 0; j < 8; j++) h[j] = __float2half_rn(tl[sc + j][d]);
        *(uint4*)(dst + (size_t)d * SQ + sc) = *(uint4*)h;   // coalesced 16B write
    }
}

__global__ void __launch_bounds__(NT, 2)
attn_mma(const float* __restrict__ Mask, float* __restrict__ O) {
    __shared__ uint32_t Ks[2][KT * RPAD];   // keys x d(halfs)
    __shared__ uint32_t Vs[2][DD * RPAD];   // d x keys(halfs)

    const int tid  = threadIdx.x;
    const int w    = tid >> 5;
    const int lane = tid & 31;
    const int g    = lane >> 2;
    const int q    = lane & 3;

    const int b  = blockIdx.y;
    const int qb = blockIdx.x * QT;
    const __half* Kg = g_Kh + (size_t)b * SQ * DD;
    const __half* Vg = g_Vt + (size_t)b * DD * SQ;

    const uint32_t ks_u = s2u(Ks);
    const uint32_t vs_u = s2u(Vs);

    auto load_kv = [&](int tile) {
        const int slot = tile & 1;
        const __half* kt = Kg + (size_t)tile * KT * DD;
        const __half* vt = Vg + tile * KT;            // V row stride SQ
        #pragma unroll
        for (int i = 0; i < 8; i++) {
            int c = tid + i * NT;                     // 0..1023
            if (c < 512) {                            // K: 64 rows x 8 chunks
                int row = c >> 3, sub = c & 7;
                cp16(ks_u + (uint32_t)(slot * KT * RPAD + row * RPAD + sub * 4) * 4,
                     kt + row * DD + sub * 8);
            } else {                                  // V: 64 rows x 8 chunks
                int c2 = c - 512;
                int row = c2 >> 3, sub = c2 & 7;
                cp16(vs_u + (uint32_t)(slot * DD * RPAD + row * RPAD + sub * 4) * 4,
                     vt + (size_t)row * SQ + sub * 8);
            }
        }
        CP_COMMIT();
    };
    load_kv(0);

    // ---- resident Q A-fragments: 2 row-blocks x 4 k-blocks x 4 regs ----
    const int r0 = qb + w * 32 + g;
    uint32_t qa[2][4][4];
    {
        const uint32_t* Qw = (const uint32_t*)(g_Qh + (size_t)b * SQ * DD);
        #pragma unroll
        for (int m = 0; m < 2; m++) {
            #pragma unroll
            for (int kb = 0; kb < 4; kb++) {
                int rr = r0 + 16 * m;
                int col = kb * 8 + q;
                qa[m][kb][0] = Qw[rr * 32 + col];
                qa[m][kb][1] = Qw[(rr + 8) * 32 + col];
                qa[m][kb][2] = Qw[rr * 32 + col + 4];
                qa[m][kb][3] = Qw[(rr + 8) * 32 + col + 4];
            }
        }
    }

    float o[2][8][4];
    #pragma unroll
    for (int m = 0; m < 2; m++)
        #pragma unroll
        for (int j = 0; j < 8; j++)
            #pragma unroll
            for (int i = 0; i < 4; i++) o[m][j][i] = 0.0f;

    float lacc[2][2] = {{0.f, 0.f}, {0.f, 0.f}};

    for (int t = 0; t < NTILES; t++) {
        const int slot = t & 1;

        CP_WAIT(0);
        __syncthreads();      // tile t staged AND every warp done with tile t-1
        if (t + 1 < NTILES) load_kv(t + 1);

        const uint32_t* Kslot = Ks[slot];
        const uint32_t* Vslot = Vs[slot];

        #pragma unroll
        for (int kk = 0; kk < 4; kk++) {      // 16 keys per kk
            uint32_t pa[2][4];

            // ---- two QK j-blocks (8 keys each) -> P fragments in registers ----
            #pragma unroll
            for (int jj = 0; jj < 2; jj++) {
                const int j = kk * 2 + jj;
                float c4[2][4] = {{0.f, 0.f, 0.f, 0.f}, {0.f, 0.f, 0.f, 0.f}};
                const uint32_t* kr = Kslot + (8 * j + g) * RPAD + q;
                #pragma unroll
                for (int kb = 0; kb < 4; kb++) {
                    uint32_t b0 = kr[kb * 8];
                    uint32_t b1 = kr[kb * 8 + 4];
                    mma_f16(c4[0], qa[0][kb][0], qa[0][kb][1], qa[0][kb][2], qa[0][kb][3], b0, b1);
                    mma_f16(c4[1], qa[1][kb][0], qa[1][kb][1], qa[1][kb][2], qa[1][kb][3], b0, b1);
                }
                #pragma unroll
                for (int m = 0; m < 2; m++) {
                    float p0 = ex2(c4[m][0]);      // logits already in log2 domain
                    float p1 = ex2(c4[m][1]);
                    float p2 = ex2(c4[m][2]);
                    float p3 = ex2(c4[m][3]);
                    lacc[m][0] += p0 + p1;
                    lacc[m][1] += p2 + p3;
                    pa[m][jj * 2]     = pk(p0, p1);
                    pa[m][jj * 2 + 1] = pk(p2, p3);
                }
            }

            // ---- O += P(kk) . V ----
            const uint32_t* vr = Vslot + kk * 8 + q;
            #pragma unroll
            for (int j2 = 0; j2 < 8; j2++) {
                uint32_t b0 = vr[(8 * j2 + g) * RPAD];
                uint32_t b1 = vr[(8 * j2 + g) * RPAD + 4];
                mma_f16(o[0][j2], pa[0][0], pa[0][1], pa[0][2], pa[0][3], b0, b1);
                mma_f16(o[1][j2], pa[1][0], pa[1][1], pa[1][2], pa[1][3], b0, b1);
            }
        }
    }

    // ---- epilogue: reduce row sums, normalize, mask, store ----
    #pragma unroll
    for (int m = 0; m < 2; m++) {
        lacc[m][0] += __shfl_xor_sync(0xffffffffu, lacc[m][0], 1);
        lacc[m][0] += __shfl_xor_sync(0xffffffffu, lacc[m][0], 2);
        lacc[m][1] += __shfl_xor_sync(0xffffffffu, lacc[m][1], 1);
        lacc[m][1] += __shfl_xor_sync(0xffffffffu, lacc[m][1], 2);

        const int row0 = r0 + 16 * m;
        const int row1 = row0 + 8;
        const float inv0 = Mask[(size_t)b * SQ + row0] / lacc[m][0];
        const float inv1 = Mask[(size_t)b * SQ + row1] / lacc[m][1];

        float* o0 = O + ((size_t)b * SQ + row0) * DD;
        float* o1 = O + ((size_t)b * SQ + row1) * DD;
        #pragma unroll
        for (int j = 0; j < 8; j++) {
            float2 v0 = make_float2(o[m][j][0] * inv0, o[m][j][1] * inv0);
            float2 v1 = make_float2(o[m][j][2] * inv1, o[m][j][3] * inv1);
            *(float2*)(o0 + 8 * j + 2 * q) = v0;
            *(float2*)(o1 + 8 * j + 2 * q) = v1;
        }
    }
}

extern "C" void kernel_launch(void* const* d_in, const int* in_sizes, int n_in,
                              void* d_out, int out_size) {
    const float* q    = (const float*)d_in[0];
    const float* k    = (const float*)d_in[1];
    const float* v    = (const float*)d_in[2];
    const float* mask = (const float*)d_in[3];
    float* out        = (float*)d_out;

    cvt_all<<<NQK + NVT, 256>>>(q, k, v);

    dim3 grid(SQ / QT, BB);
    attn_mma<<<grid, NT>>>(mask, out);
}